// round 1
// baseline (speedup 1.0000x reference)
#include <cuda_runtime.h>
#include <math.h>

// ---------------- problem constants ----------------
#define Gg   8
#define Ee   8
#define Ss   1024
#define Cc   256
#define Mdim 1024
#define Hh   5464
#define Ntok (Gg * Ss)      // 8192
#define GCv  (Gg * Cc)      // 2048 rows per expert

// ---------------- device scratch (static, allowed) ----------------
__device__ float g_expin [(size_t)Ee * GCv * Mdim];  // 64 MB
__device__ float g_hidden[(size_t)Ee * GCv * Hh];    // ~358 MB
__device__ float g_expout[(size_t)Ee * GCv * Mdim];  // 64 MB
__device__ int   g_idx1[Ntok];
__device__ int   g_idx2[Ntok];
__device__ float g_gate1[Ntok];
__device__ float g_gate2[Ntok];
__device__ int   g_slotsrc[Ee * GCv];                // [e][g][c] -> src token s or -1
__device__ int2  g_tokinfo[Ntok];                    // per token: expert_out row idx for top1/top2 or -1

// ---------------- 1) router logits + softmax + top2 ----------------
__global__ void k_router(const float* __restrict__ x, const float* __restrict__ rw) {
    int t    = (blockIdx.x * blockDim.x + threadIdx.x) >> 5;
    int lane = threadIdx.x & 31;
    if (t >= Ntok) return;
    const float* xr = x + (size_t)t * Mdim;

    float acc[Ee];
#pragma unroll
    for (int e = 0; e < Ee; e++) acc[e] = 0.f;

    for (int m = lane; m < Mdim; m += 32) {
        float xv = xr[m];
        const float4* r4 = (const float4*)(rw + m * Ee);
        float4 rA = r4[0], rB = r4[1];
        acc[0] = fmaf(xv, rA.x, acc[0]); acc[1] = fmaf(xv, rA.y, acc[1]);
        acc[2] = fmaf(xv, rA.z, acc[2]); acc[3] = fmaf(xv, rA.w, acc[3]);
        acc[4] = fmaf(xv, rB.x, acc[4]); acc[5] = fmaf(xv, rB.y, acc[5]);
        acc[6] = fmaf(xv, rB.z, acc[6]); acc[7] = fmaf(xv, rB.w, acc[7]);
    }
#pragma unroll
    for (int e = 0; e < Ee; e++) {
#pragma unroll
        for (int o = 16; o > 0; o >>= 1)
            acc[e] += __shfl_xor_sync(0xffffffffu, acc[e], o);
    }

    if (lane == 0) {
        float mx = acc[0];
#pragma unroll
        for (int e = 1; e < Ee; e++) mx = fmaxf(mx, acc[e]);
        float p[Ee]; float sum = 0.f;
#pragma unroll
        for (int e = 0; e < Ee; e++) { p[e] = expf(acc[e] - mx); sum += p[e]; }
        float inv = 1.f / sum;
#pragma unroll
        for (int e = 0; e < Ee; e++) p[e] *= inv;

        int i1 = 0; float b1 = p[0];
#pragma unroll
        for (int e = 1; e < Ee; e++) if (p[e] > b1) { b1 = p[e]; i1 = e; }
        int i2 = -1; float b2 = -1.f;
#pragma unroll
        for (int e = 0; e < Ee; e++) if (e != i1 && p[e] > b2) { b2 = p[e]; i2 = e; }

        g_idx1[t] = i1; g_idx2[t] = i2;
        g_gate1[t] = b1; g_gate2[t] = b2;
    }
}

// ---------------- 2) capacity assignment (exact cumsum semantics) ----------------
__global__ void k_capacity() {
    int g   = blockIdx.x;
    int tid = threadIdx.x;
    __shared__ int s_i1[Ss], s_i2[Ss], s_p1[Ss], s_p2[Ss];
    __shared__ int s_slot[Ee * Cc];
    __shared__ int s_cnt[Ee], s_m1c[Ee];

    for (int s = tid; s < Ss; s += blockDim.x) {
        s_i1[s] = g_idx1[g * Ss + s];
        s_i2[s] = g_idx2[g * Ss + s];
    }
    for (int i = tid; i < Ee * Cc; i += blockDim.x) s_slot[i] = -1;
    if (tid < Ee) s_cnt[tid] = 0;
    __syncthreads();

    if (tid == 0) {
        for (int s = 0; s < Ss; s++) {
            int e = s_i1[s];
            int p = s_cnt[e]++;
            if (p < Cc) { s_p1[s] = p; s_slot[e * Cc + p] = s; }
            else        { s_p1[s] = -1; }
        }
#pragma unroll
        for (int e = 0; e < Ee; e++) { s_m1c[e] = min(s_cnt[e], Cc); s_cnt[e] = 0; }
        for (int s = 0; s < Ss; s++) {
            int e = s_i2[s];
            int p = s_cnt[e]++ + s_m1c[e];
            if (p < Cc) { s_p2[s] = p; s_slot[e * Cc + p] = s; }
            else        { s_p2[s] = -1; }
        }
    }
    __syncthreads();

    for (int i = tid; i < Ee * Cc; i += blockDim.x) {
        int e = i / Cc, c = i % Cc;
        g_slotsrc[e * GCv + g * Cc + c] = s_slot[i];
    }
    for (int s = tid; s < Ss; s += blockDim.x) {
        int p1 = s_p1[s], p2 = s_p2[s];
        int e1 = s_i1[s], e2 = s_i2[s];
        int info1 = (p1 >= 0) ? (e1 * GCv + g * Cc + p1) : -1;
        int info2 = (p2 >= 0) ? (e2 * GCv + g * Cc + p2) : -1;
        g_tokinfo[g * Ss + s] = make_int2(info1, info2);
    }
}

// ---------------- 3) gather tokens into expert rows ----------------
__global__ void k_gather(const float* __restrict__ x) {
    int row = blockIdx.x;                   // e*GCv + g*Cc + c
    int g   = (row % GCv) / Cc;
    int src = g_slotsrc[row];
    float4* dst = (float4*)(g_expin + (size_t)row * Mdim);
    if (src >= 0) {
        const float4* s4 = (const float4*)(x + (size_t)(g * Ss + src) * Mdim);
        dst[threadIdx.x] = s4[threadIdx.x];
    } else {
        dst[threadIdx.x] = make_float4(0.f, 0.f, 0.f, 0.f);
    }
}

// ---------------- 4) fused dual GEMM + gelu*mul ----------------
// C[2048 x 5464] per expert; A (2048 x 1024), B0/B1 (1024 x 5464)
// tile 128x64x16, 256 threads, 8x4 per thread per output matrix
__global__ void __launch_bounds__(256) k_gemm1(const float* __restrict__ w0k,
                                               const float* __restrict__ w1k) {
    const int e  = blockIdx.z;
    const int m0 = blockIdx.y * 128;
    const int n0 = blockIdx.x * 64;
    const float* A  = g_expin + (size_t)e * GCv * Mdim;
    const float* B0 = w0k + (size_t)e * Mdim * Hh;
    const float* B1 = w1k + (size_t)e * Mdim * Hh;

    __shared__ float As[16][128];
    __shared__ float B0s[16][64];
    __shared__ float B1s[16][64];

    const int tid = threadIdx.x;
    const int tx  = tid & 15;
    const int ty  = tid >> 4;
    const int nc4 = tx * 4;

    float c0[8][4], c1[8][4];
#pragma unroll
    for (int i = 0; i < 8; i++)
#pragma unroll
        for (int j = 0; j < 4; j++) { c0[i][j] = 0.f; c1[i][j] = 0.f; }

    const int kr = tid >> 4;
    const int nb = n0 + nc4;
    const bool bok = (nb < Hh);

    for (int k0 = 0; k0 < Mdim; k0 += 16) {
#pragma unroll
        for (int it = 0; it < 2; it++) {
            int f  = tid + it * 256;
            int r  = f >> 2;
            int kq = (f & 3) * 4;
            float4 v = *(const float4*)(A + (size_t)(m0 + r) * Mdim + (k0 + kq));
            As[kq + 0][r] = v.x; As[kq + 1][r] = v.y;
            As[kq + 2][r] = v.z; As[kq + 3][r] = v.w;
        }
        {
            size_t off = (size_t)(k0 + kr) * Hh + nb;
            float4 v0 = bok ? *(const float4*)(B0 + off) : make_float4(0, 0, 0, 0);
            float4 v1 = bok ? *(const float4*)(B1 + off) : make_float4(0, 0, 0, 0);
            *(float4*)&B0s[kr][nc4] = v0;
            *(float4*)&B1s[kr][nc4] = v1;
        }
        __syncthreads();
#pragma unroll
        for (int kk = 0; kk < 16; kk++) {
            float4 a0 = *(const float4*)&As[kk][ty * 8];
            float4 a1 = *(const float4*)&As[kk][ty * 8 + 4];
            float4 b0 = *(const float4*)&B0s[kk][nc4];
            float4 b1 = *(const float4*)&B1s[kk][nc4];
            float a[8]  = {a0.x, a0.y, a0.z, a0.w, a1.x, a1.y, a1.z, a1.w};
            float p0[4] = {b0.x, b0.y, b0.z, b0.w};
            float p1[4] = {b1.x, b1.y, b1.z, b1.w};
#pragma unroll
            for (int i = 0; i < 8; i++)
#pragma unroll
                for (int j = 0; j < 4; j++) {
                    c0[i][j] = fmaf(a[i], p0[j], c0[i][j]);
                    c1[i][j] = fmaf(a[i], p1[j], c1[i][j]);
                }
        }
        __syncthreads();
    }

    float* Hbase = g_hidden + (size_t)e * GCv * Hh;
#pragma unroll
    for (int i = 0; i < 8; i++) {
        int r = m0 + ty * 8 + i;
#pragma unroll
        for (int j = 0; j < 4; j++) {
            int n = n0 + nc4 + j;
            if (n < Hh) {
                float v0 = c0[i][j], v1 = c1[i][j];
                float u = 0.7978845608028654f * (v0 + 0.044715f * v0 * v0 * v0);
                float h = 0.5f * v0 * (1.f + tanhf(u)) * v1;
                Hbase[(size_t)r * Hh + n] = h;
            }
        }
    }
}

// ---------------- 5) second GEMM: hidden @ wo ----------------
// C[2048 x 1024] per expert; A (2048 x 5464), B (5464 x 1024)
__global__ void __launch_bounds__(256) k_gemm2(const float* __restrict__ wok) {
    const int e  = blockIdx.z;
    const int m0 = blockIdx.y * 128;
    const int n0 = blockIdx.x * 64;
    const float* A = g_hidden + (size_t)e * GCv * Hh;
    const float* B = wok + (size_t)e * Hh * Mdim;

    __shared__ float As[16][128];
    __shared__ float Bs[16][64];

    const int tid = threadIdx.x;
    const int tx  = tid & 15;
    const int ty  = tid >> 4;
    const int nc4 = tx * 4;
    const int kr  = tid >> 4;

    float c[8][4];
#pragma unroll
    for (int i = 0; i < 8; i++)
#pragma unroll
        for (int j = 0; j < 4; j++) c[i][j] = 0.f;

    const int KT = (Hh + 15) / 16;   // 342, last tile partial (8 valid)
    for (int kt = 0; kt < KT; kt++) {
        int k0 = kt * 16;
#pragma unroll
        for (int it = 0; it < 2; it++) {
            int f  = tid + it * 256;
            int r  = f >> 2;
            int kq = (f & 3) * 4;
            int kcol = k0 + kq;
            float4 v = (kcol < Hh)
                ? *(const float4*)(A + (size_t)(m0 + r) * Hh + kcol)
                : make_float4(0, 0, 0, 0);
            As[kq + 0][r] = v.x; As[kq + 1][r] = v.y;
            As[kq + 2][r] = v.z; As[kq + 3][r] = v.w;
        }
        {
            int kb = k0 + kr;
            float4 v = (kb < Hh)
                ? *(const float4*)(B + (size_t)kb * Mdim + n0 + nc4)
                : make_float4(0, 0, 0, 0);
            *(float4*)&Bs[kr][nc4] = v;
        }
        __syncthreads();
#pragma unroll
        for (int kk = 0; kk < 16; kk++) {
            float4 a0 = *(const float4*)&As[kk][ty * 8];
            float4 a1 = *(const float4*)&As[kk][ty * 8 + 4];
            float4 b0 = *(const float4*)&Bs[kk][nc4];
            float a[8]  = {a0.x, a0.y, a0.z, a0.w, a1.x, a1.y, a1.z, a1.w};
            float p0[4] = {b0.x, b0.y, b0.z, b0.w};
#pragma unroll
            for (int i = 0; i < 8; i++)
#pragma unroll
                for (int j = 0; j < 4; j++)
                    c[i][j] = fmaf(a[i], p0[j], c[i][j]);
        }
        __syncthreads();
    }

    float* Obase = g_expout + (size_t)e * GCv * Mdim;
#pragma unroll
    for (int i = 0; i < 8; i++) {
        int r = m0 + ty * 8 + i;
#pragma unroll
        for (int j = 0; j < 4; j++) {
            int n = n0 + nc4 + j;
            Obase[(size_t)r * Mdim + n] = c[i][j];
        }
    }
}

// ---------------- 6) combine ----------------
__global__ void k_combine(float* __restrict__ out) {
    int t = blockIdx.x;
    int i = threadIdx.x;             // 256 threads, one float4 each (1024 floats)
    int2 info = g_tokinfo[t];
    float4 acc = make_float4(0.f, 0.f, 0.f, 0.f);
    if (info.x >= 0) {
        float gv = g_gate1[t];
        float4 v = ((const float4*)(g_expout + (size_t)info.x * Mdim))[i];
        acc.x += gv * v.x; acc.y += gv * v.y; acc.z += gv * v.z; acc.w += gv * v.w;
    }
    if (info.y >= 0) {
        float gv = g_gate2[t];
        float4 v = ((const float4*)(g_expout + (size_t)info.y * Mdim))[i];
        acc.x += gv * v.x; acc.y += gv * v.y; acc.z += gv * v.z; acc.w += gv * v.w;
    }
    ((float4*)(out + (size_t)t * Mdim))[i] = acc;
}

// ---------------- launch ----------------
extern "C" void kernel_launch(void* const* d_in, const int* in_sizes, int n_in,
                              void* d_out, int out_size) {
    const float* x  = (const float*)d_in[0];
    const float* rw = (const float*)d_in[1];
    const float* w0 = (const float*)d_in[2];
    const float* w1 = (const float*)d_in[3];
    const float* wo = (const float*)d_in[4];
    float* out = (float*)d_out;

    k_router<<<Ntok / 8, 256>>>(x, rw);
    k_capacity<<<Gg, 256>>>();
    k_gather<<<Ee * GCv, 256>>>(x);

    dim3 g1((Hh + 63) / 64, GCv / 128, Ee);   // 86 x 16 x 8
    k_gemm1<<<g1, 256>>>(w0, w1);

    dim3 g2(Mdim / 64, GCv / 128, Ee);        // 16 x 16 x 8
    k_gemm2<<<g2, 256>>>(wo);

    k_combine<<<Ntok, 256>>>(out);
}